// round 1
// baseline (speedup 1.0000x reference)
#include <cuda_runtime.h>

#define NB     32
#define NSEQ   1024
#define DMODEL 768
#define NH     12
#define DHEAD  64

// Scratch (device globals: allocation-free contract)
__device__ float g_Q[NB*NH*NSEQ*DHEAD];
__device__ float g_K[NB*NH*NSEQ*DHEAD];
__device__ float g_V[NB*NH*NSEQ*DHEAD];
__device__ float g_att[NB*NSEQ*DMODEL];

// ---------------------------------------------------------------------------
// QKV GEMM: X[32768,768] @ W[768,2304] + b  -> scatter into g_Q/g_K/g_V
// 128x128x8 tile, 256 threads, 8x8 per-thread microtile
// ---------------------------------------------------------------------------
__global__ __launch_bounds__(256) void qkv_gemm_kernel(const float* __restrict__ A,
                                                       const float* __restrict__ W,
                                                       const float* __restrict__ bias)
{
    __shared__ float As[8][128];
    __shared__ float Bs[8][128];
    const int tid = threadIdx.x;
    const int bn = blockIdx.x;   // 0..17
    const int bm = blockIdx.y;   // 0..255
    const int tx = tid & 15, ty = tid >> 4;

    const int arow = tid >> 1;
    const int acol = (tid & 1) << 2;
    const int brow = tid >> 5;
    const int bcol = (tid & 31) << 2;

    const float* Aptr = A + (bm*128 + arow)*768 + acol;
    const float* Wptr = W + brow*2304 + bn*128 + bcol;

    float acc[8][8];
    #pragma unroll
    for (int i = 0; i < 8; i++)
        #pragma unroll
        for (int j = 0; j < 8; j++) acc[i][j] = 0.f;

    for (int k0 = 0; k0 < 768; k0 += 8) {
        float4 av = *(const float4*)(Aptr + k0);
        As[acol+0][arow] = av.x;
        As[acol+1][arow] = av.y;
        As[acol+2][arow] = av.z;
        As[acol+3][arow] = av.w;
        *(float4*)&Bs[brow][bcol] = *(const float4*)(Wptr + k0*2304);
        __syncthreads();
        #pragma unroll
        for (int kk = 0; kk < 8; kk++) {
            float4 a0 = *(float4*)&As[kk][ty*8];
            float4 a1 = *(float4*)&As[kk][ty*8+4];
            float4 b0 = *(float4*)&Bs[kk][tx*8];
            float4 b1 = *(float4*)&Bs[kk][tx*8+4];
            float a[8]  = {a0.x,a0.y,a0.z,a0.w,a1.x,a1.y,a1.z,a1.w};
            float bb[8] = {b0.x,b0.y,b0.z,b0.w,b1.x,b1.y,b1.z,b1.w};
            #pragma unroll
            for (int i = 0; i < 8; i++)
                #pragma unroll
                for (int j = 0; j < 8; j++)
                    acc[i][j] += a[i]*bb[j];
        }
        __syncthreads();
    }

    #pragma unroll
    for (int i = 0; i < 8; i++) {
        const int r   = bm*128 + ty*8 + i;
        const int bb_ = r >> 10;
        const int nn  = r & 1023;
        #pragma unroll
        for (int j = 0; j < 8; j++) {
            const int c = bn*128 + tx*8 + j;
            const float v = acc[i][j] + bias[c];
            const int t   = c / 768;
            const int rem = c - t*768;
            const int hh  = rem >> 6;
            const int d   = rem & 63;
            float* dst = (t == 0) ? g_Q : (t == 1) ? g_K : g_V;
            dst[(((bb_*NH + hh) << 10) + nn)*DHEAD + d] = v;
        }
    }
}

// ---------------------------------------------------------------------------
// Flash attention: block = (qtile 64 rows, head h, batch b), 256 threads.
// Qs/KV transposed-in-smem for float4 outer-product GEMM microtiles.
// Exactly 48KB static smem -> 4 blocks/SM.
// ---------------------------------------------------------------------------
__global__ __launch_bounds__(256) void attn_kernel()
{
    __shared__ float Qs[64][64];   // Qs[d][row], pre-scaled by (1/8)*log2(e)
    __shared__ float KV[64][64];   // K phase: KV[d][col] ; V phase: KV[col][d]
    __shared__ float Ps[64][64];   // P[row][col]

    const int tid = threadIdx.x;
    const int qt = blockIdx.x;     // 0..15
    const int h  = blockIdx.y;     // 0..11
    const int b  = blockIdx.z;     // 0..31
    const int tx = tid & 15, ty = tid >> 4;

    const int bh = b*NH + h;
    const float* Qg = g_Q + (bh*NSEQ + qt*64)*DHEAD;
    const float* Kg = g_K + bh*NSEQ*DHEAD;
    const float* Vg = g_V + bh*NSEQ*DHEAD;

    const int lr  = tid >> 2;        // loader row 0..63
    const int ld0 = (tid & 3) << 4;  // loader d-offset {0,16,32,48}

    const float qscale = 0.125f * 1.44269504088896340736f;  // scale * log2(e)
    #pragma unroll
    for (int dd = 0; dd < 4; dd++) {
        float4 v = *(const float4*)(Qg + lr*64 + ld0 + dd*4);
        Qs[ld0+dd*4+0][lr] = v.x * qscale;
        Qs[ld0+dd*4+1][lr] = v.y * qscale;
        Qs[ld0+dd*4+2][lr] = v.z * qscale;
        Qs[ld0+dd*4+3][lr] = v.w * qscale;
    }

    float m[4], l[4], o[4][4];
    #pragma unroll
    for (int i = 0; i < 4; i++) {
        m[i] = -1e30f;
        l[i] = 0.f;
        #pragma unroll
        for (int j = 0; j < 4; j++) o[i][j] = 0.f;
    }

    for (int kt = 0; kt < 16; kt++) {
        __syncthreads();   // previous PV done reading KV
        {   // load K tile transposed: KV[d][col]
            const float* kp = Kg + (kt*64 + lr)*64 + ld0;
            #pragma unroll
            for (int dd = 0; dd < 4; dd++) {
                float4 v = *(const float4*)(kp + dd*4);
                KV[ld0+dd*4+0][lr] = v.x;
                KV[ld0+dd*4+1][lr] = v.y;
                KV[ld0+dd*4+2][lr] = v.z;
                KV[ld0+dd*4+3][lr] = v.w;
            }
        }
        __syncthreads();

        // S = Q K^T (already in log2 domain via qscale)
        float s[4][4];
        #pragma unroll
        for (int i = 0; i < 4; i++)
            #pragma unroll
            for (int j = 0; j < 4; j++) s[i][j] = 0.f;

        #pragma unroll 8
        for (int d = 0; d < 64; d++) {
            float4 qv = *(float4*)&Qs[d][ty*4];
            float4 kv = *(float4*)&KV[d][tx*4];
            float q[4] = {qv.x,qv.y,qv.z,qv.w};
            float k[4] = {kv.x,kv.y,kv.z,kv.w};
            #pragma unroll
            for (int i = 0; i < 4; i++)
                #pragma unroll
                for (int j = 0; j < 4; j++)
                    s[i][j] += q[i]*k[j];
        }

        // online softmax (rows live across the 16-lane tx group)
        #pragma unroll
        for (int i = 0; i < 4; i++) {
            float mx = fmaxf(fmaxf(s[i][0], s[i][1]), fmaxf(s[i][2], s[i][3]));
            #pragma unroll
            for (int off = 8; off > 0; off >>= 1)
                mx = fmaxf(mx, __shfl_xor_sync(0xffffffffu, mx, off, 16));
            const float mn = fmaxf(m[i], mx);
            const float alpha = exp2f(m[i] - mn);
            float rs = 0.f;
            #pragma unroll
            for (int j = 0; j < 4; j++) {
                const float p = exp2f(s[i][j] - mn);
                s[i][j] = p;
                rs += p;
            }
            #pragma unroll
            for (int off = 8; off > 0; off >>= 1)
                rs += __shfl_xor_sync(0xffffffffu, rs, off, 16);
            l[i] = l[i]*alpha + rs;
            m[i] = mn;
            #pragma unroll
            for (int j = 0; j < 4; j++) o[i][j] *= alpha;
        }

        #pragma unroll
        for (int i = 0; i < 4; i++)
            #pragma unroll
            for (int j = 0; j < 4; j++)
                Ps[ty*4+i][tx*4+j] = s[i][j];
        __syncthreads();   // all S-reads of KV(K) done, Ps visible

        {   // load V tile direct: KV[col][d]
            const float* vp = Vg + (kt*64 + lr)*64 + ld0;
            #pragma unroll
            for (int dd = 0; dd < 4; dd++)
                *(float4*)&KV[lr][ld0 + dd*4] = *(const float4*)(vp + dd*4);
        }
        __syncthreads();

        // O += P V
        #pragma unroll 8
        for (int c = 0; c < 64; c++) {
            float4 vv = *(float4*)&KV[c][tx*4];
            const float p0 = Ps[ty*4+0][c];
            const float p1 = Ps[ty*4+1][c];
            const float p2 = Ps[ty*4+2][c];
            const float p3 = Ps[ty*4+3][c];
            o[0][0] += p0*vv.x; o[0][1] += p0*vv.y; o[0][2] += p0*vv.z; o[0][3] += p0*vv.w;
            o[1][0] += p1*vv.x; o[1][1] += p1*vv.y; o[1][2] += p1*vv.z; o[1][3] += p1*vv.w;
            o[2][0] += p2*vv.x; o[2][1] += p2*vv.y; o[2][2] += p2*vv.z; o[2][3] += p2*vv.w;
            o[3][0] += p3*vv.x; o[3][1] += p3*vv.y; o[3][2] += p3*vv.z; o[3][3] += p3*vv.w;
        }
    }

    // normalize + write att in [B, N, H*Dh] layout (ready for proj GEMM)
    #pragma unroll
    for (int i = 0; i < 4; i++) {
        const float inv = 1.f / l[i];
        const int n = qt*64 + ty*4 + i;
        float4 r = make_float4(o[i][0]*inv, o[i][1]*inv, o[i][2]*inv, o[i][3]*inv);
        *(float4*)(g_att + (b*NSEQ + n)*DMODEL + h*DHEAD + tx*4) = r;
    }
}

// ---------------------------------------------------------------------------
// Proj GEMM: g_att[32768,768] @ Wp[768,768] + b -> out
// ---------------------------------------------------------------------------
__global__ __launch_bounds__(256) void proj_gemm_kernel(const float* __restrict__ W,
                                                        const float* __restrict__ bias,
                                                        float* __restrict__ out)
{
    __shared__ float As[8][128];
    __shared__ float Bs[8][128];
    const int tid = threadIdx.x;
    const int bn = blockIdx.x;   // 0..5
    const int bm = blockIdx.y;   // 0..255
    const int tx = tid & 15, ty = tid >> 4;

    const int arow = tid >> 1;
    const int acol = (tid & 1) << 2;
    const int brow = tid >> 5;
    const int bcol = (tid & 31) << 2;

    const float* Aptr = g_att + (bm*128 + arow)*768 + acol;
    const float* Wptr = W + brow*768 + bn*128 + bcol;

    float acc[8][8];
    #pragma unroll
    for (int i = 0; i < 8; i++)
        #pragma unroll
        for (int j = 0; j < 8; j++) acc[i][j] = 0.f;

    for (int k0 = 0; k0 < 768; k0 += 8) {
        float4 av = *(const float4*)(Aptr + k0);
        As[acol+0][arow] = av.x;
        As[acol+1][arow] = av.y;
        As[acol+2][arow] = av.z;
        As[acol+3][arow] = av.w;
        *(float4*)&Bs[brow][bcol] = *(const float4*)(Wptr + k0*768);
        __syncthreads();
        #pragma unroll
        for (int kk = 0; kk < 8; kk++) {
            float4 a0 = *(float4*)&As[kk][ty*8];
            float4 a1 = *(float4*)&As[kk][ty*8+4];
            float4 b0 = *(float4*)&Bs[kk][tx*8];
            float4 b1 = *(float4*)&Bs[kk][tx*8+4];
            float a[8]  = {a0.x,a0.y,a0.z,a0.w,a1.x,a1.y,a1.z,a1.w};
            float bb[8] = {b0.x,b0.y,b0.z,b0.w,b1.x,b1.y,b1.z,b1.w};
            #pragma unroll
            for (int i = 0; i < 8; i++)
                #pragma unroll
                for (int j = 0; j < 8; j++)
                    acc[i][j] += a[i]*bb[j];
        }
        __syncthreads();
    }

    #pragma unroll
    for (int i = 0; i < 8; i++) {
        const int r = bm*128 + ty*8 + i;
        #pragma unroll
        for (int j = 0; j < 8; j++) {
            const int c = bn*128 + tx*8 + j;
            out[r*768 + c] = acc[i][j] + bias[c];
        }
    }
}

// ---------------------------------------------------------------------------
extern "C" void kernel_launch(void* const* d_in, const int* in_sizes, int n_in,
                              void* d_out, int out_size)
{
    const float* x      = (const float*)d_in[0];
    const float* w_qkv  = (const float*)d_in[1];
    const float* b_qkv  = (const float*)d_in[2];
    const float* w_proj = (const float*)d_in[3];
    const float* b_proj = (const float*)d_in[4];
    float* out = (float*)d_out;

    qkv_gemm_kernel<<<dim3(18, 256), 256>>>(x, w_qkv, b_qkv);
    attn_kernel<<<dim3(16, NH, NB), 256>>>();
    proj_gemm_kernel<<<dim3(6, 256), 256>>>(w_proj, b_proj, out);
}

// round 5
// speedup vs baseline: 2.2804x; 2.2804x over previous
#include <cuda_runtime.h>
#include <cstdint>

#define NB     32
#define NSEQ   1024
#define DMODEL 768
#define NH     12
#define DHEAD  64

// Scratch (device globals: allocation-free contract)
__device__ float g_Q[NB*NH*NSEQ*DHEAD];
__device__ float g_K[NB*NH*NSEQ*DHEAD];
__device__ float g_V[NB*NH*NSEQ*DHEAD];
__device__ float g_att[NB*NSEQ*DMODEL];
__device__ float g_WqkvT[3*DMODEL*DMODEL];   // [2304][768] K-major
__device__ float g_WprojT[DMODEL*DMODEL];    // [768][768]  K-major

__device__ __forceinline__ uint32_t f2tf32(float f) {
    uint32_t r;
    asm("cvt.rna.tf32.f32 %0, %1;" : "=r"(r) : "f"(f));
    return r;
}

__device__ __forceinline__ void mma_tf32(float* c, const uint32_t* a, const uint32_t* b) {
    asm volatile(
        "mma.sync.aligned.m16n8k8.row.col.f32.tf32.tf32.f32 "
        "{%0,%1,%2,%3}, {%4,%5,%6,%7}, {%8,%9}, {%0,%1,%2,%3};"
        : "+f"(c[0]), "+f"(c[1]), "+f"(c[2]), "+f"(c[3])
        : "r"(a[0]), "r"(a[1]), "r"(a[2]), "r"(a[3]), "r"(b[0]), "r"(b[1]));
}

// ---------------------------------------------------------------------------
// Weight transpose: in [768][cols] -> out [cols][768]
// ---------------------------------------------------------------------------
__global__ __launch_bounds__(256) void transpose_kernel(const float* __restrict__ in,
                                                        float* __restrict__ out, int cols)
{
    __shared__ float t[32][33];
    const int x = blockIdx.x*32 + threadIdx.x;
    #pragma unroll
    for (int i = threadIdx.y; i < 32; i += 8)
        t[i][threadIdx.x] = in[(size_t)(blockIdx.y*32 + i)*cols + x];
    __syncthreads();
    const int ox = blockIdx.y*32 + threadIdx.x;
    #pragma unroll
    for (int i = threadIdx.y; i < 32; i += 8)
        out[(size_t)(blockIdx.x*32 + i)*768 + ox] = t[threadIdx.x][i];
}

// ---------------------------------------------------------------------------
// tf32 mma.sync GEMM: C[32768, NTOT] = A[32768,768] @ WT[NTOT,768]^T + bias
// 128x128 CTA tile, 8 warps of 32x64, K staged 16/iter, double buffer.
// Smem holds fragment-permuted tf32:
//   As[stage][ks*1024 + mt*128 + lane*4 + r]   (mt: 8 tiles of m16)
//   Bs[stage][ks*1024 + nt*64  + lane*2 + r]   (nt: 16 tiles of n8)
// Fragment maps (m16n8k8 tf32):
//   A reg r = ((k>>2)&1)*2 + ((m>>3)&1), lane = ((m&7)<<2)|(k&3)
//   B reg r = (k>>2)&1,                  lane = ((n&7)<<2)|(k&3)
// ---------------------------------------------------------------------------
template<int NTOT, bool SCATTER>
__global__ __launch_bounds__(256) void tc_gemm_kernel(const float* __restrict__ A,
                                                      const float* __restrict__ WT,
                                                      const float* __restrict__ bias,
                                                      float* __restrict__ out)
{
    __shared__ uint32_t As[2][2048];
    __shared__ uint32_t Bs[2][2048];

    const int tid  = threadIdx.x;
    const int lane = tid & 31;
    const int wid  = tid >> 5;
    const int wm   = wid & 3;    // m-quadrant (32 rows)
    const int wn   = wid >> 2;   // n-half (64 cols)
    const int bn   = blockIdx.x;
    const int bm   = blockIdx.y;

    // Loader geometry: row = tid>>2 (0..63, +64 for second half), kq = tid&3
    const int lm = tid >> 2;
    const int kq = tid & 3;

    const float* aptr = A  + (size_t)(bm*128 + lm)*768 + kq*4;
    const float* bptr = WT + (size_t)(bn*128 + lm)*768 + kq*4;

    auto a_off = [&](int m) {
        return (kq >> 1)*1024 + (m >> 4)*128 + ((m & 7) << 4) + ((kq & 1) << 1) + ((m >> 3) & 1);
    };
    auto b_off = [&](int n) {
        return (kq >> 1)*1024 + (n >> 3)*64 + ((n & 7) << 3) + (kq & 1);
    };
    const int ao0 = a_off(lm), ao1 = a_off(lm + 64);
    const int bo0 = b_off(lm), bo1 = b_off(lm + 64);

    float acc[2][8][4];
    #pragma unroll
    for (int i = 0; i < 2; i++)
        #pragma unroll
        for (int j = 0; j < 8; j++)
            #pragma unroll
            for (int v = 0; v < 4; v++) acc[i][j][v] = 0.f;

    float4 ra0, ra1, rb0, rb1;

    // prologue: load + stage chunk 0
    ra0 = *(const float4*)(aptr);            ra1 = *(const float4*)(aptr + 64*768);
    rb0 = *(const float4*)(bptr);            rb1 = *(const float4*)(bptr + 64*768);
    {
        uint32_t* as = As[0]; uint32_t* bs = Bs[0];
        as[ao0+0]=f2tf32(ra0.x); as[ao0+4]=f2tf32(ra0.y); as[ao0+8]=f2tf32(ra0.z); as[ao0+12]=f2tf32(ra0.w);
        as[ao1+0]=f2tf32(ra1.x); as[ao1+4]=f2tf32(ra1.y); as[ao1+8]=f2tf32(ra1.z); as[ao1+12]=f2tf32(ra1.w);
        bs[bo0+0]=f2tf32(rb0.x); bs[bo0+2]=f2tf32(rb0.y); bs[bo0+4]=f2tf32(rb0.z); bs[bo0+6]=f2tf32(rb0.w);
        bs[bo1+0]=f2tf32(rb1.x); bs[bo1+2]=f2tf32(rb1.y); bs[bo1+4]=f2tf32(rb1.z); bs[bo1+6]=f2tf32(rb1.w);
    }

    #pragma unroll 1
    for (int c = 0; c < 48; c++) {
        const int buf = c & 1;
        // issue global loads for next chunk (latency hidden by compute)
        if (c < 47) {
            const int k0 = (c + 1) * 16;
            ra0 = *(const float4*)(aptr + k0);           ra1 = *(const float4*)(aptr + k0 + 64*768);
            rb0 = *(const float4*)(bptr + k0);           rb1 = *(const float4*)(bptr + k0 + 64*768);
        }
        __syncthreads();   // stage c visible; previous compute finished (buffer free)

        // compute chunk c
        #pragma unroll
        for (int ks = 0; ks < 2; ks++) {
            const uint32_t* ab = &As[buf][ks*1024 + (wm*2)*128 + lane*4];
            uint4 a0u = *(const uint4*)(ab);
            uint4 a1u = *(const uint4*)(ab + 128);
            uint32_t a0[4] = {a0u.x, a0u.y, a0u.z, a0u.w};
            uint32_t a1[4] = {a1u.x, a1u.y, a1u.z, a1u.w};
            const uint32_t* bb = &Bs[buf][ks*1024 + (wn*8)*64 + lane*2];
            #pragma unroll
            for (int j = 0; j < 8; j++) {
                uint32_t b[2];
                b[0] = bb[j*64 + 0];
                b[1] = bb[j*64 + 1];
                mma_tf32(acc[0][j], a0, b);
                mma_tf32(acc[1][j], a1, b);
            }
        }

        // stage chunk c+1 into the other buffer
        if (c < 47) {
            uint32_t* as = As[buf ^ 1]; uint32_t* bs = Bs[buf ^ 1];
            as[ao0+0]=f2tf32(ra0.x); as[ao0+4]=f2tf32(ra0.y); as[ao0+8]=f2tf32(ra0.z); as[ao0+12]=f2tf32(ra0.w);
            as[ao1+0]=f2tf32(ra1.x); as[ao1+4]=f2tf32(ra1.y); as[ao1+8]=f2tf32(ra1.z); as[ao1+12]=f2tf32(ra1.w);
            bs[bo0+0]=f2tf32(rb0.x); bs[bo0+2]=f2tf32(rb0.y); bs[bo0+4]=f2tf32(rb0.z); bs[bo0+6]=f2tf32(rb0.w);
            bs[bo1+0]=f2tf32(rb1.x); bs[bo1+2]=f2tf32(rb1.y); bs[bo1+4]=f2tf32(rb1.z); bs[bo1+6]=f2tf32(rb1.w);
        }
    }

    // ---------------- epilogue ----------------
    const int g = lane >> 2;          // groupID (row within tile)
    const int tg = lane & 3;          // thread in group
    #pragma unroll
    for (int mt = 0; mt < 2; mt++) {
        const int row0 = bm*128 + wm*32 + mt*16 + g;
        #pragma unroll
        for (int j = 0; j < 8; j++) {
            const int col = bn*128 + wn*64 + j*8 + tg*2;
            const float2 bv = *(const float2*)(bias + col);
            float2 v0 = make_float2(acc[mt][j][0] + bv.x, acc[mt][j][1] + bv.y);
            float2 v1 = make_float2(acc[mt][j][2] + bv.x, acc[mt][j][3] + bv.y);
            if (SCATTER) {
                const int t   = col / 768;
                const int rem = col - t*768;
                const int hh  = rem >> 6;
                const int d   = rem & 63;
                float* base = (t == 0) ? g_Q : (t == 1) ? g_K : g_V;
                {
                    const int bb_ = row0 >> 10, nn = row0 & 1023;
                    *(float2*)(base + ((size_t)((bb_*NH + hh) << 10) + nn)*DHEAD + d) = v0;
                }
                {
                    const int r1 = row0 + 8;
                    const int bb_ = r1 >> 10, nn = r1 & 1023;
                    *(float2*)(base + ((size_t)((bb_*NH + hh) << 10) + nn)*DHEAD + d) = v1;
                }
            } else {
                *(float2*)(out + (size_t)row0*NTOT + col) = v0;
                *(float2*)(out + (size_t)(row0 + 8)*NTOT + col) = v1;
            }
        }
    }
}

// ---------------------------------------------------------------------------
// Flash attention (SIMT, unchanged — mma conversion is next round's lever)
// ---------------------------------------------------------------------------
__global__ __launch_bounds__(256) void attn_kernel()
{
    __shared__ float Qs[64][64];
    __shared__ float KV[64][64];
    __shared__ float Ps[64][64];

    const int tid = threadIdx.x;
    const int qt = blockIdx.x;
    const int h  = blockIdx.y;
    const int b  = blockIdx.z;
    const int tx = tid & 15, ty = tid >> 4;

    const int bh = b*NH + h;
    const float* Qg = g_Q + (bh*NSEQ + qt*64)*DHEAD;
    const float* Kg = g_K + bh*NSEQ*DHEAD;
    const float* Vg = g_V + bh*NSEQ*DHEAD;

    const int lr  = tid >> 2;
    const int ld0 = (tid & 3) << 4;

    const float qscale = 0.125f * 1.44269504088896340736f;
    #pragma unroll
    for (int dd = 0; dd < 4; dd++) {
        float4 v = *(const float4*)(Qg + lr*64 + ld0 + dd*4);
        Qs[ld0+dd*4+0][lr] = v.x * qscale;
        Qs[ld0+dd*4+1][lr] = v.y * qscale;
        Qs[ld0+dd*4+2][lr] = v.z * qscale;
        Qs[ld0+dd*4+3][lr] = v.w * qscale;
    }

    float m[4], l[4], o[4][4];
    #pragma unroll
    for (int i = 0; i < 4; i++) {
        m[i] = -1e30f;
        l[i] = 0.f;
        #pragma unroll
        for (int j = 0; j < 4; j++) o[i][j] = 0.f;
    }

    for (int kt = 0; kt < 16; kt++) {
        __syncthreads();
        {
            const float* kp = Kg + (kt*64 + lr)*64 + ld0;
            #pragma unroll
            for (int dd = 0; dd < 4; dd++) {
                float4 v = *(const float4*)(kp + dd*4);
                KV[ld0+dd*4+0][lr] = v.x;
                KV[ld0+dd*4+1][lr] = v.y;
                KV[ld0+dd*4+2][lr] = v.z;
                KV[ld0+dd*4+3][lr] = v.w;
            }
        }
        __syncthreads();

        float s[4][4];
        #pragma unroll
        for (int i = 0; i < 4; i++)
            #pragma unroll
            for (int j = 0; j < 4; j++) s[i][j] = 0.f;

        #pragma unroll 8
        for (int d = 0; d < 64; d++) {
            float4 qv = *(float4*)&Qs[d][ty*4];
            float4 kv = *(float4*)&KV[d][tx*4];
            float q[4] = {qv.x,qv.y,qv.z,qv.w};
            float k[4] = {kv.x,kv.y,kv.z,kv.w};
            #pragma unroll
            for (int i = 0; i < 4; i++)
                #pragma unroll
                for (int j = 0; j < 4; j++)
                    s[i][j] += q[i]*k[j];
        }

        #pragma unroll
        for (int i = 0; i < 4; i++) {
            float mx = fmaxf(fmaxf(s[i][0], s[i][1]), fmaxf(s[i][2], s[i][3]));
            #pragma unroll
            for (int off = 8; off > 0; off >>= 1)
                mx = fmaxf(mx, __shfl_xor_sync(0xffffffffu, mx, off, 16));
            const float mn = fmaxf(m[i], mx);
            const float alpha = exp2f(m[i] - mn);
            float rs = 0.f;
            #pragma unroll
            for (int j = 0; j < 4; j++) {
                const float p = exp2f(s[i][j] - mn);
                s[i][j] = p;
                rs += p;
            }
            #pragma unroll
            for (int off = 8; off > 0; off >>= 1)
                rs += __shfl_xor_sync(0xffffffffu, rs, off, 16);
            l[i] = l[i]*alpha + rs;
            m[i] = mn;
            #pragma unroll
            for (int j = 0; j < 4; j++) o[i][j] *= alpha;
        }

        #pragma unroll
        for (int i = 0; i < 4; i++)
            #pragma unroll
            for (int j = 0; j < 4; j++)
                Ps[ty*4+i][tx*4+j] = s[i][j];
        __syncthreads();

        {
            const float* vp = Vg + (kt*64 + lr)*64 + ld0;
            #pragma unroll
            for (int dd = 0; dd < 4; dd++)
                *(float4*)&KV[lr][ld0 + dd*4] = *(const float4*)(vp + dd*4);
        }
        __syncthreads();

        #pragma unroll 8
        for (int c = 0; c < 64; c++) {
            float4 vv = *(float4*)&KV[c][tx*4];
            const float p0 = Ps[ty*4+0][c];
            const float p1 = Ps[ty*4+1][c];
            const float p2 = Ps[ty*4+2][c];
            const float p3 = Ps[ty*4+3][c];
            o[0][0] += p0*vv.x; o[0][1] += p0*vv.y; o[0][2] += p0*vv.z; o[0][3] += p0*vv.w;
            o[1][0] += p1*vv.x; o[1][1] += p1*vv.y; o[1][2] += p1*vv.z; o[1][3] += p1*vv.w;
            o[2][0] += p2*vv.x; o[2][1] += p2*vv.y; o[2][2] += p2*vv.z; o[2][3] += p2*vv.w;
            o[3][0] += p3*vv.x; o[3][1] += p3*vv.y; o[3][2] += p3*vv.z; o[3][3] += p3*vv.w;
        }
    }

    #pragma unroll
    for (int i = 0; i < 4; i++) {
        const float inv = 1.f / l[i];
        const int n = qt*64 + ty*4 + i;
        float4 r = make_float4(o[i][0]*inv, o[i][1]*inv, o[i][2]*inv, o[i][3]*inv);
        *(float4*)(g_att + (b*NSEQ + n)*DMODEL + h*DHEAD + tx*4) = r;
    }
}

// ---------------------------------------------------------------------------
extern "C" void kernel_launch(void* const* d_in, const int* in_sizes, int n_in,
                              void* d_out, int out_size)
{
    const float* x      = (const float*)d_in[0];
    const float* w_qkv  = (const float*)d_in[1];
    const float* b_qkv  = (const float*)d_in[2];
    const float* w_proj = (const float*)d_in[3];
    const float* b_proj = (const float*)d_in[4];
    float* out = (float*)d_out;

    float* wqkvT  = nullptr;
    float* wprojT = nullptr;
    float* attbuf = nullptr;
    cudaGetSymbolAddress((void**)&wqkvT,  g_WqkvT);
    cudaGetSymbolAddress((void**)&wprojT, g_WprojT);
    cudaGetSymbolAddress((void**)&attbuf, g_att);

    transpose_kernel<<<dim3(72, 24), dim3(32, 8)>>>(w_qkv, wqkvT, 2304);
    transpose_kernel<<<dim3(24, 24), dim3(32, 8)>>>(w_proj, wprojT, 768);

    tc_gemm_kernel<2304, true><<<dim3(18, 256), 256>>>(x, wqkvT, b_qkv, nullptr);
    attn_kernel<<<dim3(16, NH, NB), 256>>>();
    tc_gemm_kernel<768, false><<<dim3(6, 256), 256>>>(attbuf, wprojT, b_proj, out);
}

// round 6
// speedup vs baseline: 3.0738x; 1.3479x over previous
#include <cuda_runtime.h>
#include <cstdint>

#define NB     32
#define NSEQ   1024
#define DMODEL 768
#define NH     12
#define DHEAD  64

// Scratch (device globals: allocation-free contract)
__device__ float g_Q[NB*NH*NSEQ*DHEAD];
__device__ float g_K[NB*NH*NSEQ*DHEAD];
__device__ float g_V[NB*NH*NSEQ*DHEAD];
__device__ float g_att[NB*NSEQ*DMODEL];
__device__ float g_WqkvT[3*DMODEL*DMODEL];   // [2304][768] K-major
__device__ float g_WprojT[DMODEL*DMODEL];    // [768][768]  K-major

__device__ __forceinline__ uint32_t f2tf32(float f) {
    uint32_t r;
    asm("cvt.rna.tf32.f32 %0, %1;" : "=r"(r) : "f"(f));
    return r;
}

__device__ __forceinline__ void mma_tf32(float* c, const uint32_t* a, const uint32_t* b) {
    asm volatile(
        "mma.sync.aligned.m16n8k8.row.col.f32.tf32.tf32.f32 "
        "{%0,%1,%2,%3}, {%4,%5,%6,%7}, {%8,%9}, {%0,%1,%2,%3};"
        : "+f"(c[0]), "+f"(c[1]), "+f"(c[2]), "+f"(c[3])
        : "r"(a[0]), "r"(a[1]), "r"(a[2]), "r"(a[3]), "r"(b[0]), "r"(b[1]));
}

// ---------------------------------------------------------------------------
// Weight transpose: in [768][cols] -> out [cols][768]
// ---------------------------------------------------------------------------
__global__ __launch_bounds__(256) void transpose_kernel(const float* __restrict__ in,
                                                        float* __restrict__ out, int cols)
{
    __shared__ float t[32][33];
    const int x = blockIdx.x*32 + threadIdx.x;
    #pragma unroll
    for (int i = threadIdx.y; i < 32; i += 8)
        t[i][threadIdx.x] = in[(size_t)(blockIdx.y*32 + i)*cols + x];
    __syncthreads();
    const int ox = blockIdx.y*32 + threadIdx.x;
    #pragma unroll
    for (int i = threadIdx.y; i < 32; i += 8)
        out[(size_t)(blockIdx.x*32 + i)*768 + ox] = t[threadIdx.x][i];
}

// ---------------------------------------------------------------------------
// tf32 mma.sync GEMM (unchanged from R5, proven): C = A @ WT^T + bias
// ---------------------------------------------------------------------------
template<int NTOT, bool SCATTER>
__global__ __launch_bounds__(256) void tc_gemm_kernel(const float* __restrict__ A,
                                                      const float* __restrict__ WT,
                                                      const float* __restrict__ bias,
                                                      float* __restrict__ out)
{
    __shared__ uint32_t As[2][2048];
    __shared__ uint32_t Bs[2][2048];

    const int tid  = threadIdx.x;
    const int lane = tid & 31;
    const int wid  = tid >> 5;
    const int wm   = wid & 3;
    const int wn   = wid >> 2;
    const int bn   = blockIdx.x;
    const int bm   = blockIdx.y;

    const int lm = tid >> 2;
    const int kq = tid & 3;

    const float* aptr = A  + (size_t)(bm*128 + lm)*768 + kq*4;
    const float* bptr = WT + (size_t)(bn*128 + lm)*768 + kq*4;

    auto a_off = [&](int m) {
        return (kq >> 1)*1024 + (m >> 4)*128 + ((m & 7) << 4) + ((kq & 1) << 1) + ((m >> 3) & 1);
    };
    auto b_off = [&](int n) {
        return (kq >> 1)*1024 + (n >> 3)*64 + ((n & 7) << 3) + (kq & 1);
    };
    const int ao0 = a_off(lm), ao1 = a_off(lm + 64);
    const int bo0 = b_off(lm), bo1 = b_off(lm + 64);

    float acc[2][8][4];
    #pragma unroll
    for (int i = 0; i < 2; i++)
        #pragma unroll
        for (int j = 0; j < 8; j++)
            #pragma unroll
            for (int v = 0; v < 4; v++) acc[i][j][v] = 0.f;

    float4 ra0, ra1, rb0, rb1;

    ra0 = *(const float4*)(aptr);            ra1 = *(const float4*)(aptr + 64*768);
    rb0 = *(const float4*)(bptr);            rb1 = *(const float4*)(bptr + 64*768);
    {
        uint32_t* as = As[0]; uint32_t* bs = Bs[0];
        as[ao0+0]=f2tf32(ra0.x); as[ao0+4]=f2tf32(ra0.y); as[ao0+8]=f2tf32(ra0.z); as[ao0+12]=f2tf32(ra0.w);
        as[ao1+0]=f2tf32(ra1.x); as[ao1+4]=f2tf32(ra1.y); as[ao1+8]=f2tf32(ra1.z); as[ao1+12]=f2tf32(ra1.w);
        bs[bo0+0]=f2tf32(rb0.x); bs[bo0+2]=f2tf32(rb0.y); bs[bo0+4]=f2tf32(rb0.z); bs[bo0+6]=f2tf32(rb0.w);
        bs[bo1+0]=f2tf32(rb1.x); bs[bo1+2]=f2tf32(rb1.y); bs[bo1+4]=f2tf32(rb1.z); bs[bo1+6]=f2tf32(rb1.w);
    }

    #pragma unroll 1
    for (int c = 0; c < 48; c++) {
        const int buf = c & 1;
        if (c < 47) {
            const int k0 = (c + 1) * 16;
            ra0 = *(const float4*)(aptr + k0);           ra1 = *(const float4*)(aptr + k0 + 64*768);
            rb0 = *(const float4*)(bptr + k0);           rb1 = *(const float4*)(bptr + k0 + 64*768);
        }
        __syncthreads();

        #pragma unroll
        for (int ks = 0; ks < 2; ks++) {
            const uint32_t* ab = &As[buf][ks*1024 + (wm*2)*128 + lane*4];
            uint4 a0u = *(const uint4*)(ab);
            uint4 a1u = *(const uint4*)(ab + 128);
            uint32_t a0[4] = {a0u.x, a0u.y, a0u.z, a0u.w};
            uint32_t a1[4] = {a1u.x, a1u.y, a1u.z, a1u.w};
            const uint32_t* bb = &Bs[buf][ks*1024 + (wn*8)*64 + lane*2];
            #pragma unroll
            for (int j = 0; j < 8; j++) {
                uint32_t b[2];
                b[0] = bb[j*64 + 0];
                b[1] = bb[j*64 + 1];
                mma_tf32(acc[0][j], a0, b);
                mma_tf32(acc[1][j], a1, b);
            }
        }

        if (c < 47) {
            uint32_t* as = As[buf ^ 1]; uint32_t* bs = Bs[buf ^ 1];
            as[ao0+0]=f2tf32(ra0.x); as[ao0+4]=f2tf32(ra0.y); as[ao0+8]=f2tf32(ra0.z); as[ao0+12]=f2tf32(ra0.w);
            as[ao1+0]=f2tf32(ra1.x); as[ao1+4]=f2tf32(ra1.y); as[ao1+8]=f2tf32(ra1.z); as[ao1+12]=f2tf32(ra1.w);
            bs[bo0+0]=f2tf32(rb0.x); bs[bo0+2]=f2tf32(rb0.y); bs[bo0+4]=f2tf32(rb0.z); bs[bo0+6]=f2tf32(rb0.w);
            bs[bo1+0]=f2tf32(rb1.x); bs[bo1+2]=f2tf32(rb1.y); bs[bo1+4]=f2tf32(rb1.z); bs[bo1+6]=f2tf32(rb1.w);
        }
    }

    const int g = lane >> 2;
    const int tg = lane & 3;
    #pragma unroll
    for (int mt = 0; mt < 2; mt++) {
        const int row0 = bm*128 + wm*32 + mt*16 + g;
        #pragma unroll
        for (int j = 0; j < 8; j++) {
            const int col = bn*128 + wn*64 + j*8 + tg*2;
            const float2 bv = *(const float2*)(bias + col);
            float2 v0 = make_float2(acc[mt][j][0] + bv.x, acc[mt][j][1] + bv.y);
            float2 v1 = make_float2(acc[mt][j][2] + bv.x, acc[mt][j][3] + bv.y);
            if (SCATTER) {
                const int t   = col / 768;
                const int rem = col - t*768;
                const int hh  = rem >> 6;
                const int d   = rem & 63;
                float* base = (t == 0) ? g_Q : (t == 1) ? g_K : g_V;
                {
                    const int bb_ = row0 >> 10, nn = row0 & 1023;
                    *(float2*)(base + ((size_t)((bb_*NH + hh) << 10) + nn)*DHEAD + d) = v0;
                }
                {
                    const int r1 = row0 + 8;
                    const int bb_ = r1 >> 10, nn = r1 & 1023;
                    *(float2*)(base + ((size_t)((bb_*NH + hh) << 10) + nn)*DHEAD + d) = v1;
                }
            } else {
                *(float2*)(out + (size_t)row0*NTOT + col) = v0;
                *(float2*)(out + (size_t)(row0 + 8)*NTOT + col) = v1;
            }
        }
    }
}

// ---------------------------------------------------------------------------
// mma-based flash attention.
// CTA: 64-query tile of one (b,h). 8 warps: 4(m16) x 2(n32). 16 k-tiles of 64.
// S = Qhi*K + Qlo*K  (split-Q: Q exact, only K carries tf32 rounding)
// P tf32 -> smem (A-frag layout), O += P*V via mma.
// Smem (uint32 words):
//   QHI 0..4095 | QLO 4096..8191 | KS 8192..12287 | VS 12288..16383
//   PS 16384..20479 | RMX 20480..20607 (f32 [64][2]) | RSM 20608..20735
// Frag-permuted index maps (validated by the GEMM kernel):
//   A(m,k): (k>>3)*512 + ((m>>4)<<7) + ((m&7)<<4) + ((k&3)<<2) + (((k>>2)&1)<<1) + ((m>>3)&1)
//   B(n,k): (k>>3)*512 + ((n>>3)<<6) + ((n&7)<<3) + ((k&3)<<1) + ((k>>2)&1)
// ---------------------------------------------------------------------------
#define ATTN_SMEM_WORDS 20736
#define ATTN_SMEM_BYTES (ATTN_SMEM_WORDS*4)
#define QHI_OFF 0
#define QLO_OFF 4096
#define KS_OFF  8192
#define VS_OFF  12288
#define PS_OFF  16384
#define RMX_OFF 20480
#define RSM_OFF 20608

__global__ __launch_bounds__(256, 2) void attn_mma_kernel()
{
    extern __shared__ uint32_t sm[];
    float* rmx = (float*)(sm + RMX_OFF);
    float* rsm = (float*)(sm + RSM_OFF);

    const int tid  = threadIdx.x;
    const int lane = tid & 31;
    const int wid  = tid >> 5;
    const int mw   = wid & 3;     // m16 block (rows mw*16..)
    const int nw   = wid >> 2;    // n32 block (cols nw*32..)
    const int g    = lane >> 2;
    const int tg   = lane & 3;

    const int qt = blockIdx.x;
    const int h  = blockIdx.y;
    const int b  = blockIdx.z;
    const int bh = b*NH + h;

    const float* Qg = g_Q + ((size_t)bh*NSEQ + qt*64)*DHEAD;
    const float* Kg = g_K + (size_t)bh*NSEQ*DHEAD;
    const float* Vg = g_V + (size_t)bh*NSEQ*DHEAD;

    // ---- stage Q (scaled, hi/lo split) ----
    const int lr = tid >> 2;          // 0..63
    const int ds = (tid & 3) << 4;    // 0,16,32,48
    const float qscale = 0.125f * 1.44269504088896340736f;
    #pragma unroll
    for (int j = 0; j < 4; j++) {
        const int d0 = ds + j*4;
        float4 v = *(const float4*)(Qg + lr*64 + d0);
        float q[4] = {v.x*qscale, v.y*qscale, v.z*qscale, v.w*qscale};
        const int base = (d0 >> 3)*512 + ((lr >> 4) << 7) + ((lr & 7) << 4)
                       + (((d0 >> 2) & 1) << 1) + ((lr >> 3) & 1);
        #pragma unroll
        for (int e = 0; e < 4; e++) {
            uint32_t hi = f2tf32(q[e]);
            sm[QHI_OFF + base + e*4] = hi;
            sm[QLO_OFF + base + e*4] = f2tf32(q[e] - __uint_as_float(hi));
        }
    }

    float m0 = -1e30f, m1 = -1e30f, l0 = 0.f, l1 = 0.f;
    float O[4][4];
    #pragma unroll
    for (int nt = 0; nt < 4; nt++)
        #pragma unroll
        for (int v = 0; v < 4; v++) O[nt][v] = 0.f;

    const int r0 = mw*16 + g;     // row within q-tile
    const int r1 = r0 + 8;

    #pragma unroll 1
    for (int kt = 0; kt < 16; kt++) {
        __syncthreads();   // prev PV done with VS, prev S done with KS (also covers Q staging on kt=0)

        // ---- stage K, V tiles (64 keys x 64 d) ----
        {
            const float* kp = Kg + (size_t)(kt*64 + lr)*64;
            const float* vp = Vg + (size_t)(kt*64 + lr)*64;
            #pragma unroll
            for (int j = 0; j < 4; j++) {
                const int d0 = ds + j*4;
                float4 kv = *(const float4*)(kp + d0);
                float4 vv = *(const float4*)(vp + d0);
                // K: B-frag (n=key=lr, k=d)
                const int kb = (d0 >> 3)*512 + ((lr >> 3) << 6) + ((lr & 7) << 3) + ((d0 >> 2) & 1);
                sm[KS_OFF + kb + 0] = f2tf32(kv.x);
                sm[KS_OFF + kb + 2] = f2tf32(kv.y);
                sm[KS_OFF + kb + 4] = f2tf32(kv.z);
                sm[KS_OFF + kb + 6] = f2tf32(kv.w);
                // V: B-frag (n=d, k=key=lr)
                const int vb = (lr >> 3)*512 + ((d0 >> 3) << 6) + ((d0 & 7) << 3)
                             + ((lr & 3) << 1) + ((lr >> 2) & 1);
                sm[VS_OFF + vb + 0]  = f2tf32(vv.x);
                sm[VS_OFF + vb + 8]  = f2tf32(vv.y);
                sm[VS_OFF + vb + 16] = f2tf32(vv.z);
                sm[VS_OFF + vb + 24] = f2tf32(vv.w);
            }
        }
        __syncthreads();

        // ---- S = Qhi*K + Qlo*K ----
        float acc[4][4];
        #pragma unroll
        for (int nt = 0; nt < 4; nt++)
            #pragma unroll
            for (int v = 0; v < 4; v++) acc[nt][v] = 0.f;

        #pragma unroll
        for (int kb = 0; kb < 8; kb++) {
            uint4 hu = *(const uint4*)(sm + QHI_OFF + kb*512 + mw*128 + lane*4);
            uint4 lu = *(const uint4*)(sm + QLO_OFF + kb*512 + mw*128 + lane*4);
            uint32_t ah[4] = {hu.x, hu.y, hu.z, hu.w};
            uint32_t al[4] = {lu.x, lu.y, lu.z, lu.w};
            #pragma unroll
            for (int nt = 0; nt < 4; nt++) {
                const uint32_t* bp = sm + KS_OFF + kb*512 + (nw*4 + nt)*64 + lane*2;
                uint32_t bfr[2] = {bp[0], bp[1]};
                mma_tf32(acc[nt], ah, bfr);
                mma_tf32(acc[nt], al, bfr);
            }
        }

        // ---- online softmax (cross-warp via smem partials) ----
        float mx0 = acc[0][0], mx1 = acc[0][2];
        #pragma unroll
        for (int nt = 0; nt < 4; nt++) {
            mx0 = fmaxf(mx0, fmaxf(acc[nt][0], acc[nt][1]));
            mx1 = fmaxf(mx1, fmaxf(acc[nt][2], acc[nt][3]));
        }
        #pragma unroll
        for (int off = 1; off <= 2; off <<= 1) {
            mx0 = fmaxf(mx0, __shfl_xor_sync(0xffffffffu, mx0, off));
            mx1 = fmaxf(mx1, __shfl_xor_sync(0xffffffffu, mx1, off));
        }
        if (tg == 0) {
            rmx[r0*2 + nw] = mx0;
            rmx[r1*2 + nw] = mx1;
        }
        __syncthreads();

        const float M0 = fmaxf(rmx[r0*2], rmx[r0*2 + 1]);
        const float M1 = fmaxf(rmx[r1*2], rmx[r1*2 + 1]);
        const float mn0 = fmaxf(m0, M0), mn1 = fmaxf(m1, M1);
        const float al0 = exp2f(m0 - mn0), al1 = exp2f(m1 - mn1);
        m0 = mn0; m1 = mn1;

        float s0 = 0.f, s1 = 0.f;
        #pragma unroll
        for (int nt = 0; nt < 4; nt++) {
            float p00 = exp2f(acc[nt][0] - mn0);
            float p01 = exp2f(acc[nt][1] - mn0);
            float p10 = exp2f(acc[nt][2] - mn1);
            float p11 = exp2f(acc[nt][3] - mn1);
            s0 += p00 + p01;
            s1 += p10 + p11;
            const int c0 = nw*32 + nt*8 + 2*tg;
            // P into A-frag layout (m = r0/r1, k = c)
            #pragma unroll
            for (int jj = 0; jj < 2; jj++) {
                const int c = c0 + jj;
                const int pb = (c >> 3)*512 + ((c & 3) << 2) + (((c >> 2) & 1) << 1);
                const float pv0 = (jj == 0) ? p00 : p01;
                const float pv1 = (jj == 0) ? p10 : p11;
                sm[PS_OFF + pb + ((r0 >> 4) << 7) + ((r0 & 7) << 4) + ((r0 >> 3) & 1)] = f2tf32(pv0);
                sm[PS_OFF + pb + ((r1 >> 4) << 7) + ((r1 & 7) << 4) + ((r1 >> 3) & 1)] = f2tf32(pv1);
            }
        }
        #pragma unroll
        for (int off = 1; off <= 2; off <<= 1) {
            s0 += __shfl_xor_sync(0xffffffffu, s0, off);
            s1 += __shfl_xor_sync(0xffffffffu, s1, off);
        }
        if (tg == 0) {
            rsm[r0*2 + nw] = s0;
            rsm[r1*2 + nw] = s1;
        }
        __syncthreads();

        l0 = l0*al0 + rsm[r0*2] + rsm[r0*2 + 1];
        l1 = l1*al1 + rsm[r1*2] + rsm[r1*2 + 1];
        #pragma unroll
        for (int nt = 0; nt < 4; nt++) {
            O[nt][0] *= al0; O[nt][1] *= al0;
            O[nt][2] *= al1; O[nt][3] *= al1;
        }

        // ---- O += P * V ----
        #pragma unroll
        for (int kb = 0; kb < 8; kb++) {
            uint4 au = *(const uint4*)(sm + PS_OFF + kb*512 + mw*128 + lane*4);
            uint32_t a[4] = {au.x, au.y, au.z, au.w};
            #pragma unroll
            for (int nt = 0; nt < 4; nt++) {
                const uint32_t* bp = sm + VS_OFF + kb*512 + (nw*4 + nt)*64 + lane*2;
                uint32_t bfr[2] = {bp[0], bp[1]};
                mma_tf32(O[nt], a, bfr);
            }
        }
    }

    // ---- normalize + store ----
    const float inv0 = 1.f / l0;
    const float inv1 = 1.f / l1;
    const int row0 = qt*64 + r0;
    #pragma unroll
    for (int nt = 0; nt < 4; nt++) {
        const int col = nw*32 + nt*8 + 2*tg;
        float* o0 = g_att + ((size_t)b*NSEQ + row0)*DMODEL + h*64 + col;
        float* o1 = g_att + ((size_t)b*NSEQ + row0 + 8)*DMODEL + h*64 + col;
        *(float2*)o0 = make_float2(O[nt][0]*inv0, O[nt][1]*inv0);
        *(float2*)o1 = make_float2(O[nt][2]*inv1, O[nt][3]*inv1);
    }
}

// ---------------------------------------------------------------------------
extern "C" void kernel_launch(void* const* d_in, const int* in_sizes, int n_in,
                              void* d_out, int out_size)
{
    const float* x      = (const float*)d_in[0];
    const float* w_qkv  = (const float*)d_in[1];
    const float* b_qkv  = (const float*)d_in[2];
    const float* w_proj = (const float*)d_in[3];
    const float* b_proj = (const float*)d_in[4];
    float* out = (float*)d_out;

    cudaFuncSetAttribute(attn_mma_kernel,
                         cudaFuncAttributeMaxDynamicSharedMemorySize, ATTN_SMEM_BYTES);

    float* wqkvT  = nullptr;
    float* wprojT = nullptr;
    float* attbuf = nullptr;
    cudaGetSymbolAddress((void**)&wqkvT,  g_WqkvT);
    cudaGetSymbolAddress((void**)&wprojT, g_WprojT);
    cudaGetSymbolAddress((void**)&attbuf, g_att);

    transpose_kernel<<<dim3(72, 24), dim3(32, 8)>>>(w_qkv, wqkvT, 2304);
    transpose_kernel<<<dim3(24, 24), dim3(32, 8)>>>(w_proj, wprojT, 768);

    tc_gemm_kernel<2304, true><<<dim3(18, 256), 256>>>(x, wqkvT, b_qkv, nullptr);
    attn_mma_kernel<<<dim3(16, NH, NB), 256, ATTN_SMEM_BYTES>>>();
    tc_gemm_kernel<768, false><<<dim3(6, 256), 256>>>(attbuf, wprojT, b_proj, out);
}

// round 7
// speedup vs baseline: 4.2190x; 1.3725x over previous
#include <cuda_runtime.h>
#include <cstdint>

#define NB     32
#define NSEQ   1024
#define DMODEL 768
#define NH     12
#define DHEAD  64

// Scratch (device globals: allocation-free contract)
__device__ float g_Q[NB*NH*NSEQ*DHEAD];
__device__ float g_K[NB*NH*NSEQ*DHEAD];
__device__ float g_Vt[NB*NH*DHEAD*NSEQ];     // V transposed: [b,h,d,n]
__device__ float g_att[NB*NSEQ*DMODEL];
__device__ float g_WqkvT[3*DMODEL*DMODEL];   // [2304][768] K-major
__device__ float g_WprojT[DMODEL*DMODEL];    // [768][768]  K-major

__device__ __forceinline__ uint32_t f2tf32(float f) {
    uint32_t r;
    asm("cvt.rna.tf32.f32 %0, %1;" : "=r"(r) : "f"(f));
    return r;
}

__device__ __forceinline__ void mma_tf32(float* c, const uint32_t* a, const uint32_t* b) {
    asm volatile(
        "mma.sync.aligned.m16n8k8.row.col.f32.tf32.tf32.f32 "
        "{%0,%1,%2,%3}, {%4,%5,%6,%7}, {%8,%9}, {%0,%1,%2,%3};"
        : "+f"(c[0]), "+f"(c[1]), "+f"(c[2]), "+f"(c[3])
        : "r"(a[0]), "r"(a[1]), "r"(a[2]), "r"(a[3]), "r"(b[0]), "r"(b[1]));
}

// ---------------------------------------------------------------------------
// Weight transpose: in [768][cols] -> out [cols][768]
// ---------------------------------------------------------------------------
__global__ __launch_bounds__(256) void transpose_kernel(const float* __restrict__ in,
                                                        float* __restrict__ out, int cols)
{
    __shared__ float t[32][33];
    const int x = blockIdx.x*32 + threadIdx.x;
    #pragma unroll
    for (int i = threadIdx.y; i < 32; i += 8)
        t[i][threadIdx.x] = in[(size_t)(blockIdx.y*32 + i)*cols + x];
    __syncthreads();
    const int ox = blockIdx.y*32 + threadIdx.x;
    #pragma unroll
    for (int i = threadIdx.y; i < 32; i += 8)
        out[(size_t)(blockIdx.x*32 + i)*768 + ox] = t[threadIdx.x][i];
}

// ---------------------------------------------------------------------------
// tf32 mma.sync GEMM (proven): C = A @ WT^T + bias
// SCATTER writes Q/K in [b,h,n,d] and V TRANSPOSED in [b,h,d,n].
// ---------------------------------------------------------------------------
template<int NTOT, bool SCATTER>
__global__ __launch_bounds__(256) void tc_gemm_kernel(const float* __restrict__ A,
                                                      const float* __restrict__ WT,
                                                      const float* __restrict__ bias,
                                                      float* __restrict__ out)
{
    __shared__ uint32_t As[2][2048];
    __shared__ uint32_t Bs[2][2048];

    const int tid  = threadIdx.x;
    const int lane = tid & 31;
    const int wid  = tid >> 5;
    const int wm   = wid & 3;
    const int wn   = wid >> 2;
    const int bn   = blockIdx.x;
    const int bm   = blockIdx.y;

    const int lm = tid >> 2;
    const int kq = tid & 3;

    const float* aptr = A  + (size_t)(bm*128 + lm)*768 + kq*4;
    const float* bptr = WT + (size_t)(bn*128 + lm)*768 + kq*4;

    auto a_off = [&](int m) {
        return (kq >> 1)*1024 + (m >> 4)*128 + ((m & 7) << 4) + ((kq & 1) << 1) + ((m >> 3) & 1);
    };
    auto b_off = [&](int n) {
        return (kq >> 1)*1024 + (n >> 3)*64 + ((n & 7) << 3) + (kq & 1);
    };
    const int ao0 = a_off(lm), ao1 = a_off(lm + 64);
    const int bo0 = b_off(lm), bo1 = b_off(lm + 64);

    float acc[2][8][4];
    #pragma unroll
    for (int i = 0; i < 2; i++)
        #pragma unroll
        for (int j = 0; j < 8; j++)
            #pragma unroll
            for (int v = 0; v < 4; v++) acc[i][j][v] = 0.f;

    float4 ra0, ra1, rb0, rb1;

    ra0 = *(const float4*)(aptr);            ra1 = *(const float4*)(aptr + 64*768);
    rb0 = *(const float4*)(bptr);            rb1 = *(const float4*)(bptr + 64*768);
    {
        uint32_t* as = As[0]; uint32_t* bs = Bs[0];
        as[ao0+0]=f2tf32(ra0.x); as[ao0+4]=f2tf32(ra0.y); as[ao0+8]=f2tf32(ra0.z); as[ao0+12]=f2tf32(ra0.w);
        as[ao1+0]=f2tf32(ra1.x); as[ao1+4]=f2tf32(ra1.y); as[ao1+8]=f2tf32(ra1.z); as[ao1+12]=f2tf32(ra1.w);
        bs[bo0+0]=f2tf32(rb0.x); bs[bo0+2]=f2tf32(rb0.y); bs[bo0+4]=f2tf32(rb0.z); bs[bo0+6]=f2tf32(rb0.w);
        bs[bo1+0]=f2tf32(rb1.x); bs[bo1+2]=f2tf32(rb1.y); bs[bo1+4]=f2tf32(rb1.z); bs[bo1+6]=f2tf32(rb1.w);
    }

    #pragma unroll 1
    for (int c = 0; c < 48; c++) {
        const int buf = c & 1;
        if (c < 47) {
            const int k0 = (c + 1) * 16;
            ra0 = *(const float4*)(aptr + k0);           ra1 = *(const float4*)(aptr + k0 + 64*768);
            rb0 = *(const float4*)(bptr + k0);           rb1 = *(const float4*)(bptr + k0 + 64*768);
        }
        __syncthreads();

        #pragma unroll
        for (int ks = 0; ks < 2; ks++) {
            const uint32_t* ab = &As[buf][ks*1024 + (wm*2)*128 + lane*4];
            uint4 a0u = *(const uint4*)(ab);
            uint4 a1u = *(const uint4*)(ab + 128);
            uint32_t a0[4] = {a0u.x, a0u.y, a0u.z, a0u.w};
            uint32_t a1[4] = {a1u.x, a1u.y, a1u.z, a1u.w};
            const uint32_t* bb = &Bs[buf][ks*1024 + (wn*8)*64 + lane*2];
            #pragma unroll
            for (int j = 0; j < 8; j++) {
                uint32_t b[2];
                b[0] = bb[j*64 + 0];
                b[1] = bb[j*64 + 1];
                mma_tf32(acc[0][j], a0, b);
                mma_tf32(acc[1][j], a1, b);
            }
        }

        if (c < 47) {
            uint32_t* as = As[buf ^ 1]; uint32_t* bs = Bs[buf ^ 1];
            as[ao0+0]=f2tf32(ra0.x); as[ao0+4]=f2tf32(ra0.y); as[ao0+8]=f2tf32(ra0.z); as[ao0+12]=f2tf32(ra0.w);
            as[ao1+0]=f2tf32(ra1.x); as[ao1+4]=f2tf32(ra1.y); as[ao1+8]=f2tf32(ra1.z); as[ao1+12]=f2tf32(ra1.w);
            bs[bo0+0]=f2tf32(rb0.x); bs[bo0+2]=f2tf32(rb0.y); bs[bo0+4]=f2tf32(rb0.z); bs[bo0+6]=f2tf32(rb0.w);
            bs[bo1+0]=f2tf32(rb1.x); bs[bo1+2]=f2tf32(rb1.y); bs[bo1+4]=f2tf32(rb1.z); bs[bo1+6]=f2tf32(rb1.w);
        }
    }

    const int g = lane >> 2;
    const int tg = lane & 3;
    #pragma unroll
    for (int mt = 0; mt < 2; mt++) {
        const int row0 = bm*128 + wm*32 + mt*16 + g;
        #pragma unroll
        for (int j = 0; j < 8; j++) {
            const int col = bn*128 + wn*64 + j*8 + tg*2;
            const float2 bv = *(const float2*)(bias + col);
            float2 v0 = make_float2(acc[mt][j][0] + bv.x, acc[mt][j][1] + bv.y);
            float2 v1 = make_float2(acc[mt][j][2] + bv.x, acc[mt][j][3] + bv.y);
            if (SCATTER) {
                const int t   = col / 768;
                const int rem = col - t*768;
                const int hh  = rem >> 6;
                const int d   = rem & 63;
                const int bb_ = row0 >> 10;
                const int nn0 = row0 & 1023;
                const int nn1 = (row0 + 8) & 1023;
                const int bh  = bb_*NH + hh;
                if (t == 2) {
                    // V transposed: [bh][d][n]
                    float* vb = g_Vt + ((size_t)bh*DHEAD + d)*NSEQ;
                    vb[nn0]        = v0.x;
                    vb[NSEQ + nn0] = v0.y;
                    vb[nn1]        = v1.x;
                    vb[NSEQ + nn1] = v1.y;
                } else {
                    float* base = (t == 0) ? g_Q : g_K;
                    float* dst = base + ((size_t)bh*NSEQ)*DHEAD + d;
                    *(float2*)(dst + (size_t)nn0*DHEAD) = v0;
                    *(float2*)(dst + (size_t)nn1*DHEAD) = v1;
                }
            } else {
                *(float2*)(out + (size_t)row0*NTOT + col) = v0;
                *(float2*)(out + (size_t)(row0 + 8)*NTOT + col) = v1;
            }
        }
    }
}

// ---------------------------------------------------------------------------
// mma flash attention v2: Q-tile 128, 8 warps x m16, each warp all 64 keys.
// - K/V staged via STS.128 with XOR swizzle (conflict-free)
// - warp-private online softmax (no cross-warp smem partials)
// - P converted c-frag -> A-frag via shuffles (no smem round trip)
// Smem (words): QHI 8*1024 | QLO 8*1024 | KS 8*512 | VS 8*512  = 24576 (96KB)
// B-region layout per k8 block kb (512 words):
//   word = ((n>>3)<<6) + (((n&7)^kb)<<3) + [ (((k&3)<<1)|((k>>2)&1)) ^ (kb&4) ]
// ---------------------------------------------------------------------------
#define AQHI 0
#define AQLO 8192
#define AKS  16384
#define AVS  20480
#define ATTN_SMEM_BYTES (24576*4)

__global__ __launch_bounds__(256, 2) void attn_mma2_kernel()
{
    extern __shared__ uint32_t sm[];

    const int tid  = threadIdx.x;
    const int lane = tid & 31;
    const int w    = tid >> 5;       // warp 0..7 -> rows w*16..+16
    const int g    = lane >> 2;
    const int tg   = lane & 3;

    const int qt = blockIdx.x;       // 0..7 (128-query tiles)
    const int h  = blockIdx.y;
    const int b  = blockIdx.z;
    const int bh = b*NH + h;

    const float* Qg  = g_Q  + ((size_t)bh*NSEQ + qt*128)*DHEAD;
    const float* Kg  = g_K  + (size_t)bh*NSEQ*DHEAD;
    const float* Vtg = g_Vt + (size_t)bh*DHEAD*NSEQ;

    // ---- stage Q (scaled, hi/lo split) into A-frag layout (once) ----
    {
        const int row = tid >> 1;           // 0..127
        const int kh  = (tid & 1) * 32;     // k half
        const float qscale = 0.125f * 1.44269504088896340736f;
        #pragma unroll
        for (int j4 = 0; j4 < 8; j4++) {
            const int k0 = kh + j4*4;
            float4 v = *(const float4*)(Qg + row*64 + k0);
            float q[4] = {v.x*qscale, v.y*qscale, v.z*qscale, v.w*qscale};
            const int kb  = k0 >> 3;
            const int par = (k0 >> 2) & 1;
            const int base = kb*1024 + ((row >> 4) << 7) + ((row & 7) << 4)
                           + (par << 1) + ((row >> 3) & 1);
            #pragma unroll
            for (int e = 0; e < 4; e++) {
                uint32_t hi = f2tf32(q[e]);
                sm[AQHI + base + (e << 2)] = hi;
                sm[AQLO + base + (e << 2)] = f2tf32(q[e] - __uint_as_float(hi));
            }
        }
    }

    float m0 = -1e30f, m1 = -1e30f, l0 = 0.f, l1 = 0.f;
    float O[8][4];
    #pragma unroll
    for (int nt = 0; nt < 8; nt++)
        #pragma unroll
        for (int v = 0; v < 4; v++) O[nt][v] = 0.f;

    const int srcA = (lane & 28) | (tg >> 1);
    const int srcB = srcA + 2;
    const int nrow = lane >> 3;       // 0..3
    const int kbl  = lane & 7;        // staging k8-block
    const int sbase_off = ((nrow & 7) ^ kbl) << 3;   // note: full (n&7) added per rep
    const int oo = kbl & 4;

    #pragma unroll 1
    for (int kt = 0; kt < 16; kt++) {
        __syncthreads();   // everyone done reading KS/VS (and Q staged, kt=0)

        // ---- stage K and Vt tiles (64x64 each), conflict-free STS.128 ----
        #pragma unroll
        for (int rep = 0; rep < 2; rep++) {
            const int n = w*4 + rep*32 + nrow;   // key (K) / d (V)
            const int slot = ((n & 7) ^ kbl) << 3;
            const int rbase = (kbl << 9) + ((n >> 3) << 6) + slot;
            {
                const float4* kp = (const float4*)(Kg + (size_t)(kt*64 + n)*64 + kbl*8);
                float4 v0 = kp[0], v1 = kp[1];
                uint4 q0 = make_uint4(f2tf32(v0.x), f2tf32(v1.x), f2tf32(v0.y), f2tf32(v1.y));
                uint4 q1 = make_uint4(f2tf32(v0.z), f2tf32(v1.z), f2tf32(v0.w), f2tf32(v1.w));
                *(uint4*)(sm + AKS + rbase + oo)       = q0;
                *(uint4*)(sm + AKS + rbase + (oo ^ 4)) = q1;
            }
            {
                const float4* vp = (const float4*)(Vtg + (size_t)n*NSEQ + kt*64 + kbl*8);
                float4 v0 = vp[0], v1 = vp[1];
                uint4 q0 = make_uint4(f2tf32(v0.x), f2tf32(v1.x), f2tf32(v0.y), f2tf32(v1.y));
                uint4 q1 = make_uint4(f2tf32(v0.z), f2tf32(v1.z), f2tf32(v0.w), f2tf32(v1.w));
                *(uint4*)(sm + AVS + rbase + oo)       = q0;
                *(uint4*)(sm + AVS + rbase + (oo ^ 4)) = q1;
            }
        }
        __syncthreads();

        // ---- S = Qhi*K + Qlo*K ----
        float acc[8][4];
        #pragma unroll
        for (int nt = 0; nt < 8; nt++)
            #pragma unroll
            for (int v = 0; v < 4; v++) acc[nt][v] = 0.f;

        #pragma unroll
        for (int kb = 0; kb < 8; kb++) {
            uint4 hu = *(const uint4*)(sm + AQHI + kb*1024 + w*128 + lane*4);
            uint4 lu = *(const uint4*)(sm + AQLO + kb*1024 + w*128 + lane*4);
            uint32_t ah[4] = {hu.x, hu.y, hu.z, hu.w};
            uint32_t al[4] = {lu.x, lu.y, lu.z, lu.w};
            const int lx = (lane*2) ^ ((kb << 3) | (kb & 4));
            #pragma unroll
            for (int nt = 0; nt < 8; nt++) {
                const uint32_t* bp = sm + AKS + kb*512 + nt*64 + lx;
                uint32_t bf[2] = {bp[0], bp[1]};
                mma_tf32(acc[nt], ah, bf);
                mma_tf32(acc[nt], al, bf);
            }
        }

        // ---- warp-private online softmax ----
        float mx0 = -1e30f, mx1 = -1e30f;
        #pragma unroll
        for (int nt = 0; nt < 8; nt++) {
            mx0 = fmaxf(mx0, fmaxf(acc[nt][0], acc[nt][1]));
            mx1 = fmaxf(mx1, fmaxf(acc[nt][2], acc[nt][3]));
        }
        mx0 = fmaxf(mx0, __shfl_xor_sync(0xffffffffu, mx0, 1));
        mx0 = fmaxf(mx0, __shfl_xor_sync(0xffffffffu, mx0, 2));
        mx1 = fmaxf(mx1, __shfl_xor_sync(0xffffffffu, mx1, 1));
        mx1 = fmaxf(mx1, __shfl_xor_sync(0xffffffffu, mx1, 2));

        const float mn0 = fmaxf(m0, mx0), mn1 = fmaxf(m1, mx1);
        const float al0 = exp2f(m0 - mn0), al1 = exp2f(m1 - mn1);
        m0 = mn0; m1 = mn1;

        float s0 = 0.f, s1 = 0.f;
        #pragma unroll
        for (int nt = 0; nt < 8; nt++) {
            acc[nt][0] = exp2f(acc[nt][0] - mn0);
            acc[nt][1] = exp2f(acc[nt][1] - mn0);
            acc[nt][2] = exp2f(acc[nt][2] - mn1);
            acc[nt][3] = exp2f(acc[nt][3] - mn1);
            s0 += acc[nt][0] + acc[nt][1];
            s1 += acc[nt][2] + acc[nt][3];
        }
        s0 += __shfl_xor_sync(0xffffffffu, s0, 1);
        s0 += __shfl_xor_sync(0xffffffffu, s0, 2);
        s1 += __shfl_xor_sync(0xffffffffu, s1, 1);
        s1 += __shfl_xor_sync(0xffffffffu, s1, 2);
        l0 = l0*al0 + s0;
        l1 = l1*al1 + s1;

        #pragma unroll
        for (int nt = 0; nt < 8; nt++) {
            O[nt][0] *= al0; O[nt][1] *= al0;
            O[nt][2] *= al1; O[nt][3] *= al1;
        }

        // ---- O += P*V : P c-frag -> A-frag via shuffles, V from smem ----
        const bool odd = (tg & 1);
        #pragma unroll
        for (int nt = 0; nt < 8; nt++) {
            float u00 = __shfl_sync(0xffffffffu, acc[nt][0], srcA);
            float u01 = __shfl_sync(0xffffffffu, acc[nt][1], srcA);
            float u10 = __shfl_sync(0xffffffffu, acc[nt][2], srcA);
            float u11 = __shfl_sync(0xffffffffu, acc[nt][3], srcA);
            float v00 = __shfl_sync(0xffffffffu, acc[nt][0], srcB);
            float v01 = __shfl_sync(0xffffffffu, acc[nt][1], srcB);
            float v10 = __shfl_sync(0xffffffffu, acc[nt][2], srcB);
            float v11 = __shfl_sync(0xffffffffu, acc[nt][3], srcB);
            uint32_t a[4];
            a[0] = f2tf32(odd ? u01 : u00);
            a[1] = f2tf32(odd ? u11 : u10);
            a[2] = f2tf32(odd ? v01 : v00);
            a[3] = f2tf32(odd ? v11 : v10);
            const int lx = (lane*2) ^ ((nt << 3) | (nt & 4));
            #pragma unroll
            for (int ntd = 0; ntd < 8; ntd++) {
                const uint32_t* bp = sm + AVS + nt*512 + ntd*64 + lx;
                uint32_t bf[2] = {bp[0], bp[1]};
                mma_tf32(O[ntd], a, bf);
            }
        }
    }

    // ---- normalize + store ----
    const float inv0 = 1.f / l0;
    const float inv1 = 1.f / l1;
    const int row0 = qt*128 + w*16 + g;
    #pragma unroll
    for (int ntd = 0; ntd < 8; ntd++) {
        const int col = ntd*8 + 2*tg;
        float* o0 = g_att + ((size_t)b*NSEQ + row0)*DMODEL + h*64 + col;
        float* o1 = g_att + ((size_t)b*NSEQ + row0 + 8)*DMODEL + h*64 + col;
        *(float2*)o0 = make_float2(O[ntd][0]*inv0, O[ntd][1]*inv0);
        *(float2*)o1 = make_float2(O[ntd][2]*inv1, O[ntd][3]*inv1);
    }
}

// ---------------------------------------------------------------------------
extern "C" void kernel_launch(void* const* d_in, const int* in_sizes, int n_in,
                              void* d_out, int out_size)
{
    const float* x      = (const float*)d_in[0];
    const float* w_qkv  = (const float*)d_in[1];
    const float* b_qkv  = (const float*)d_in[2];
    const float* w_proj = (const float*)d_in[3];
    const float* b_proj = (const float*)d_in[4];
    float* out = (float*)d_out;

    cudaFuncSetAttribute(attn_mma2_kernel,
                         cudaFuncAttributeMaxDynamicSharedMemorySize, ATTN_SMEM_BYTES);

    float* wqkvT  = nullptr;
    float* wprojT = nullptr;
    float* attbuf = nullptr;
    cudaGetSymbolAddress((void**)&wqkvT,  g_WqkvT);
    cudaGetSymbolAddress((void**)&wprojT, g_WprojT);
    cudaGetSymbolAddress((void**)&attbuf, g_att);

    transpose_kernel<<<dim3(72, 24), dim3(32, 8)>>>(w_qkv, wqkvT, 2304);
    transpose_kernel<<<dim3(24, 24), dim3(32, 8)>>>(w_proj, wprojT, 768);

    tc_gemm_kernel<2304, true><<<dim3(18, 256), 256>>>(x, wqkvT, b_qkv, nullptr);
    attn_mma2_kernel<<<dim3(8, NH, NB), 256, ATTN_SMEM_BYTES>>>();
    tc_gemm_kernel<768, false><<<dim3(6, 256), 256>>>(attbuf, wprojT, b_proj, out);
}